// round 9
// baseline (speedup 1.0000x reference)
#include <cuda_runtime.h>
#include <math.h>

// Problem constants
#define NN        512
#define ROWS      256
#define BM        32
#define BN        32
#define BK        32
#define NTILES    128          // (ROWS/BM)*(NN/BN)
#define KSPLIT    4
#define KCHUNK    128
#define THREADS   256

#define SAMPLE_ELEMS 131072
#define STD_BYTES    268435456ull        // 256*512*512 * 4B
#define MS_CHUNKS    4
#define MS_BYTES     (STD_BYTES / MS_CHUNKS)      // 64 MB
#define DIAG_PER_CH  (SAMPLE_ELEMS / MS_CHUNKS)   // 32768 diag entries per chunk

// Split-K partial sums and softplus scratch
__device__ float g_pv[KSPLIT][ROWS][NN];
__device__ float g_pm[KSPLIT][ROWS][NN];
__device__ float g_sp[SAMPLE_ELEMS];

__global__ __launch_bounds__(THREADS)
void gemm_stage1(const float* __restrict__ x,
                 const float* __restrict__ W)
{
    __shared__ float Xs[BM][BK + 1];
    __shared__ float Wv[BN][BK + 1];
    __shared__ float Wm[BN][BK + 1];

    const int tile  = blockIdx.x & 127;
    const int chunk = blockIdx.x >> 7;
    const int bm    = tile >> 4;
    const int bn    = tile & 15;
    const int row0  = bm * BM;
    const int n0    = bn * BN;
    const int kbeg  = chunk * KCHUNK;

    const int tid = threadIdx.x;
    const int tx  = tid & 15;
    const int ty  = tid >> 4;
    const int rl  = ty * 2;
    const int nl  = tx * 2;

    const int lr = tid >> 3;
    const int lc = (tid & 7) * 4;

    float av[2][2] = {{0.f,0.f},{0.f,0.f}};
    float am[2][2] = {{0.f,0.f},{0.f,0.f}};

    for (int k0 = kbeg; k0 < kbeg + KCHUNK; k0 += BK) {
        float4 xv = *reinterpret_cast<const float4*>(&x[(size_t)(row0 + lr) * NN + k0 + lc]);
        Xs[lr][lc + 0] = xv.x; Xs[lr][lc + 1] = xv.y;
        Xs[lr][lc + 2] = xv.z; Xs[lr][lc + 3] = xv.w;

        float4 wv = *reinterpret_cast<const float4*>(&W[(size_t)(n0 + lr) * NN + k0 + lc]);
        Wv[lr][lc + 0] = wv.x; Wv[lr][lc + 1] = wv.y;
        Wv[lr][lc + 2] = wv.z; Wv[lr][lc + 3] = wv.w;

        float4 wm = *reinterpret_cast<const float4*>(&W[(size_t)(512 + n0 + lr) * NN + k0 + lc]);
        Wm[lr][lc + 0] = wm.x; Wm[lr][lc + 1] = wm.y;
        Wm[lr][lc + 2] = wm.z; Wm[lr][lc + 3] = wm.w;

        __syncthreads();

        #pragma unroll
        for (int kk = 0; kk < BK; kk++) {
            float x0 = Xs[rl][kk],     x1 = Xs[rl + 1][kk];
            float v0 = Wv[nl][kk],     v1 = Wv[nl + 1][kk];
            float m0 = Wm[nl][kk],     m1 = Wm[nl + 1][kk];
            av[0][0] += x0 * v0;  av[0][1] += x0 * v1;
            av[1][0] += x1 * v0;  av[1][1] += x1 * v1;
            am[0][0] += x0 * m0;  am[0][1] += x0 * m1;
            am[1][0] += x1 * m0;  am[1][1] += x1 * m1;
        }
        __syncthreads();
    }

    #pragma unroll
    for (int rr = 0; rr < 2; rr++) {
        #pragma unroll
        for (int nn = 0; nn < 2; nn++) {
            g_pv[chunk][row0 + rl + rr][n0 + nl + nn] = av[rr][nn];
            g_pm[chunk][row0 + rl + rr][n0 + nl + nn] = am[rr][nn];
        }
    }
}

// Combine partials -> sample, mu, softplus scratch (doesn't touch std_mat)
__global__ __launch_bounds__(THREADS)
void combine_sm(const float* __restrict__ b,
                const float* __restrict__ eps,
                float* __restrict__ out)
{
    float* __restrict__ outS = out;
    float* __restrict__ outM = out + SAMPLE_ELEMS;

    const unsigned i = blockIdx.x * THREADS + threadIdx.x;
    const unsigned r = i >> 9;
    const unsigned n = i & 511u;

    float v = ((g_pv[0][r][n] + g_pv[1][r][n]) + (g_pv[2][r][n] + g_pv[3][r][n])) + b[n];
    float m = ((g_pm[0][r][n] + g_pm[1][r][n]) + (g_pm[2][r][n] + g_pm[3][r][n])) + b[512 + n];
    float sp = (v > 20.f) ? v : log1pf(expf(v));

    outM[i] = m;
    outS[i] = m + sqrtf(sp) * eps[i];
    g_sp[i] = sp;
}

// Scatter one chunk's worth of diagonal values over the freshly-zeroed region
__global__ __launch_bounds__(THREADS)
void diag_fixup_chunk(float* __restrict__ out, unsigned chunk)
{
    float* __restrict__ outD = out + 2 * SAMPLE_ELEMS;
    const unsigned i = chunk * DIAG_PER_CH + blockIdx.x * THREADS + threadIdx.x;
    outD[(size_t)i * NN + (i & 511u)] = g_sp[i];
}

extern "C" void kernel_launch(void* const* d_in, const int* in_sizes, int n_in,
                              void* d_out, int out_size)
{
    const float* x   = (const float*)d_in[0];
    const float* W   = (const float*)d_in[1];
    const float* b   = (const float*)d_in[2];
    const float* eps = (const float*)d_in[3];
    float* out = (float*)d_out;

    (void)in_sizes; (void)n_in; (void)out_size;

    // One-time resources, created on the first (correctness) call — before graph capture.
    static cudaStream_t s_cmp = nullptr;   // compute branch
    static cudaStream_t s_fix = nullptr;   // fixup pipeline branch
    static cudaEvent_t  e_fork = nullptr;
    static cudaEvent_t  e_cmp  = nullptr;
    static cudaEvent_t  e_fx   = nullptr;
    static cudaEvent_t  e_ms[MS_CHUNKS] = {nullptr, nullptr, nullptr, nullptr};
    if (s_cmp == nullptr) {
        cudaStreamCreateWithFlags(&s_cmp, cudaStreamNonBlocking);
        cudaStreamCreateWithFlags(&s_fix, cudaStreamNonBlocking);
        cudaEventCreateWithFlags(&e_fork, cudaEventDisableTiming);
        cudaEventCreateWithFlags(&e_cmp,  cudaEventDisableTiming);
        cudaEventCreateWithFlags(&e_fx,   cudaEventDisableTiming);
        for (int c = 0; c < MS_CHUNKS; c++)
            cudaEventCreateWithFlags(&e_ms[c], cudaEventDisableTiming);
    }

    char* std_base = reinterpret_cast<char*>(out + 2 * SAMPLE_ELEMS);

    // Fork compute branch
    cudaEventRecord(e_fork, 0);
    cudaStreamWaitEvent(s_cmp, e_fork, 0);
    gemm_stage1<<<NTILES * KSPLIT, THREADS, 0, s_cmp>>>(x, W);
    combine_sm<<<SAMPLE_ELEMS / THREADS, THREADS, 0, s_cmp>>>(b, eps, out);
    cudaEventRecord(e_cmp, s_cmp);

    // Legacy stream: 4 serial engine-fill chunks (fast memset path proven in R4)
    for (int c = 0; c < MS_CHUNKS; c++) {
        cudaMemsetAsync(std_base + (size_t)c * MS_BYTES, 0, MS_BYTES);
        cudaEventRecord(e_ms[c], 0);
    }

    // Fixup pipeline: chunks 0..2 scatter their diagonals while later fills run
    cudaStreamWaitEvent(s_fix, e_cmp, 0);
    for (unsigned c = 0; c < MS_CHUNKS - 1; c++) {
        cudaStreamWaitEvent(s_fix, e_ms[c], 0);
        diag_fixup_chunk<<<DIAG_PER_CH / THREADS, THREADS, 0, s_fix>>>(out, c);
    }
    cudaEventRecord(e_fx, s_fix);

    // Tail on legacy stream: only the last chunk's fixup remains serial
    cudaStreamWaitEvent(0, e_fx, 0);
    cudaStreamWaitEvent(0, e_cmp, 0);
    diag_fixup_chunk<<<DIAG_PER_CH / THREADS, THREADS>>>(out, MS_CHUNKS - 1);
}

// round 11
// speedup vs baseline: 1.0013x; 1.0013x over previous
#include <cuda_runtime.h>
#include <math.h>

// Problem constants
#define NN        512
#define ROWS      256
#define BM        32
#define BN        32
#define BK        32
#define NTILES    128
#define KSPLIT    4
#define KCHUNK    128
#define THREADS   256

#define SAMPLE_ELEMS 131072
#define STD_BYTES    268435456ull        // 256 MB
#define ENG_BYTES    167772160ull        // 160 MB zeroed by copy engine
#define SM_QUAD0     10485760u           // ENG_BYTES/16 : first quad of SM region
#define SM_QUADS_END 16777216u           // STD_BYTES/16
#define FILL_BLOCKS  592                 // 4 * 148 SMs
#define FILL_CHUNKQ  2048u               // 256 threads * 8 quads per chunk
#define FILL_CHUNKS  3072u               // (SM_QUADS_END - SM_QUAD0) / FILL_CHUNKQ

// Split-K partial sums and softplus scratch
__device__ float g_pv[KSPLIT][ROWS][NN];
__device__ float g_pm[KSPLIT][ROWS][NN];
__device__ float g_sp[SAMPLE_ELEMS];

__global__ __launch_bounds__(THREADS)
void gemm_stage1(const float* __restrict__ x,
                 const float* __restrict__ W)
{
    __shared__ float Xs[BM][BK + 1];
    __shared__ float Wv[BN][BK + 1];
    __shared__ float Wm[BN][BK + 1];

    const int tile  = blockIdx.x & 127;
    const int chunk = blockIdx.x >> 7;
    const int bm    = tile >> 4;
    const int bn    = tile & 15;
    const int row0  = bm * BM;
    const int n0    = bn * BN;
    const int kbeg  = chunk * KCHUNK;

    const int tid = threadIdx.x;
    const int tx  = tid & 15;
    const int ty  = tid >> 4;
    const int rl  = ty * 2;
    const int nl  = tx * 2;

    const int lr = tid >> 3;
    const int lc = (tid & 7) * 4;

    float av[2][2] = {{0.f,0.f},{0.f,0.f}};
    float am[2][2] = {{0.f,0.f},{0.f,0.f}};

    for (int k0 = kbeg; k0 < kbeg + KCHUNK; k0 += BK) {
        float4 xv = *reinterpret_cast<const float4*>(&x[(size_t)(row0 + lr) * NN + k0 + lc]);
        Xs[lr][lc + 0] = xv.x; Xs[lr][lc + 1] = xv.y;
        Xs[lr][lc + 2] = xv.z; Xs[lr][lc + 3] = xv.w;

        float4 wv = *reinterpret_cast<const float4*>(&W[(size_t)(n0 + lr) * NN + k0 + lc]);
        Wv[lr][lc + 0] = wv.x; Wv[lr][lc + 1] = wv.y;
        Wv[lr][lc + 2] = wv.z; Wv[lr][lc + 3] = wv.w;

        float4 wm = *reinterpret_cast<const float4*>(&W[(size_t)(512 + n0 + lr) * NN + k0 + lc]);
        Wm[lr][lc + 0] = wm.x; Wm[lr][lc + 1] = wm.y;
        Wm[lr][lc + 2] = wm.z; Wm[lr][lc + 3] = wm.w;

        __syncthreads();

        #pragma unroll
        for (int kk = 0; kk < BK; kk++) {
            float x0 = Xs[rl][kk],     x1 = Xs[rl + 1][kk];
            float v0 = Wv[nl][kk],     v1 = Wv[nl + 1][kk];
            float m0 = Wm[nl][kk],     m1 = Wm[nl + 1][kk];
            av[0][0] += x0 * v0;  av[0][1] += x0 * v1;
            av[1][0] += x1 * v0;  av[1][1] += x1 * v1;
            am[0][0] += x0 * m0;  am[0][1] += x0 * m1;
            am[1][0] += x1 * m0;  am[1][1] += x1 * m1;
        }
        __syncthreads();
    }

    #pragma unroll
    for (int rr = 0; rr < 2; rr++) {
        #pragma unroll
        for (int nn = 0; nn < 2; nn++) {
            g_pv[chunk][row0 + rl + rr][n0 + nl + nn] = av[rr][nn];
            g_pm[chunk][row0 + rl + rr][n0 + nl + nn] = am[rr][nn];
        }
    }
}

// Combine partials -> sample, mu, softplus scratch (doesn't touch std_mat)
__global__ __launch_bounds__(THREADS)
void combine_sm(const float* __restrict__ b,
                const float* __restrict__ eps,
                float* __restrict__ out)
{
    float* __restrict__ outS = out;
    float* __restrict__ outM = out + SAMPLE_ELEMS;

    const unsigned i = blockIdx.x * THREADS + threadIdx.x;
    const unsigned r = i >> 9;
    const unsigned n = i & 511u;

    float v = ((g_pv[0][r][n] + g_pv[1][r][n]) + (g_pv[2][r][n] + g_pv[3][r][n])) + b[n];
    float m = ((g_pm[0][r][n] + g_pm[1][r][n]) + (g_pm[2][r][n] + g_pm[3][r][n])) + b[512 + n];
    float sp = (v > 20.f) ? v : log1pf(expf(v));

    outM[i] = m;
    outS[i] = m + sqrtf(sp) * eps[i];
    g_sp[i] = sp;
}

// SM fill: zero the tail region [ENG_BYTES, STD_BYTES) with a lean store loop
__global__ __launch_bounds__(THREADS)
void sm_fill(float* __restrict__ out)
{
    float4* __restrict__ d4 = reinterpret_cast<float4*>(out + 2 * SAMPLE_ELEMS);
    const float4 z = make_float4(0.f, 0.f, 0.f, 0.f);
    for (unsigned c = blockIdx.x; c < FILL_CHUNKS; c += FILL_BLOCKS) {
        float4* p = d4 + SM_QUAD0 + (size_t)c * FILL_CHUNKQ + threadIdx.x;
        #pragma unroll
        for (int k = 0; k < 8; k++)
            p[k * THREADS] = z;
    }
}

// Scatter the softplus diagonal over the zeroed std_mat
__global__ __launch_bounds__(THREADS)
void diag_fixup(float* __restrict__ out)
{
    float* __restrict__ outD = out + 2 * SAMPLE_ELEMS;
    const unsigned i = blockIdx.x * THREADS + threadIdx.x;   // 0..131071
    outD[(size_t)i * NN + (i & 511u)] = g_sp[i];
}

extern "C" void kernel_launch(void* const* d_in, const int* in_sizes, int n_in,
                              void* d_out, int out_size)
{
    const float* x   = (const float*)d_in[0];
    const float* W   = (const float*)d_in[1];
    const float* b   = (const float*)d_in[2];
    const float* eps = (const float*)d_in[3];
    float* out = (float*)d_out;

    (void)in_sizes; (void)n_in; (void)out_size;

    // One-time resources, created on the first (correctness) call — before graph capture.
    static cudaStream_t s_cmp  = nullptr;   // compute branch (gemm -> combine)
    static cudaStream_t s_fill = nullptr;   // SM fill branch
    static cudaEvent_t  e_fork = nullptr;
    static cudaEvent_t  e_cmp  = nullptr;
    static cudaEvent_t  e_fill = nullptr;
    if (s_cmp == nullptr) {
        cudaStreamCreateWithFlags(&s_cmp,  cudaStreamNonBlocking);
        cudaStreamCreateWithFlags(&s_fill, cudaStreamNonBlocking);
        cudaEventCreateWithFlags(&e_fork, cudaEventDisableTiming);
        cudaEventCreateWithFlags(&e_cmp,  cudaEventDisableTiming);
        cudaEventCreateWithFlags(&e_fill, cudaEventDisableTiming);
    }

    char* std_base = reinterpret_cast<char*>(out + 2 * SAMPLE_ELEMS);

    // Fork
    cudaEventRecord(e_fork, 0);
    cudaStreamWaitEvent(s_cmp,  e_fork, 0);
    cudaStreamWaitEvent(s_fill, e_fork, 0);

    // Branch A (SMs): zero the tail 96 MB of std_mat
    sm_fill<<<FILL_BLOCKS, THREADS, 0, s_fill>>>(out);
    cudaEventRecord(e_fill, s_fill);

    // Branch B (SMs): split-K GEMM then combine (sample, mu, softplus scratch)
    gemm_stage1<<<NTILES * KSPLIT, THREADS, 0, s_cmp>>>(x, W);
    combine_sm<<<SAMPLE_ELEMS / THREADS, THREADS, 0, s_cmp>>>(b, eps, out);
    cudaEventRecord(e_cmp, s_cmp);

    // Branch C (copy engine, legacy stream): zero the first 160 MB
    cudaMemsetAsync(std_base, 0, ENG_BYTES);

    // Join on legacy stream: diag scatter after all three branches
    cudaStreamWaitEvent(0, e_fill, 0);
    cudaStreamWaitEvent(0, e_cmp, 0);
    diag_fixup<<<SAMPLE_ELEMS / THREADS, THREADS>>>(out);
}

// round 13
// speedup vs baseline: 1.2083x; 1.2067x over previous
#include <cuda_runtime.h>
#include <math.h>

// Problem constants
#define NN        512
#define ROWS      256
#define BM        32
#define BN        32
#define BK        32
#define NB_GEMM   128          // 8 row tiles * 16 n tiles
#define THREADS   256

#define SAMPLE_ELEMS 131072
#define STD_BYTES    268435456ull        // 256 MB
#define MSA_BYTES    167772160ull        // 160 MB first phase
// diag entry i sits at float offset i*512 + (i&511); i < 81920 -> inside first 160MB
#define DIAG_SPLIT   81920u
#define FIXA_BLOCKS  (DIAG_SPLIT / THREADS)                    // 320
#define FIXB_BLOCKS  ((SAMPLE_ELEMS - DIAG_SPLIT) / THREADS)   // 192

// softplus diagonal scratch
__device__ float g_sp[SAMPLE_ELEMS];

__global__ __launch_bounds__(THREADS)
void gaussian_sampler_gemm(const float* __restrict__ x,
                           const float* __restrict__ W,
                           const float* __restrict__ b,
                           const float* __restrict__ eps,
                           float* __restrict__ out)
{
    float* __restrict__ outS = out;                       // sample
    float* __restrict__ outM = out + SAMPLE_ELEMS;        // mu

    __shared__ float Xs[BM][BK + 1];
    __shared__ float Wv[BN][BK + 1];
    __shared__ float Wm[BN][BK + 1];

    const int bm   = blockIdx.x >> 4;
    const int bn   = blockIdx.x & 15;
    const int row0 = bm * BM;
    const int n0   = bn * BN;

    const int tid = threadIdx.x;
    const int tx  = tid & 15;
    const int ty  = tid >> 4;
    const int rl  = ty * 2;
    const int nl  = tx * 2;

    const int lr = tid >> 3;
    const int lc = (tid & 7) * 4;

    float av[2][2] = {{0.f,0.f},{0.f,0.f}};
    float am[2][2] = {{0.f,0.f},{0.f,0.f}};

    for (int k0 = 0; k0 < NN; k0 += BK) {
        float4 xv = *reinterpret_cast<const float4*>(&x[(size_t)(row0 + lr) * NN + k0 + lc]);
        Xs[lr][lc + 0] = xv.x; Xs[lr][lc + 1] = xv.y;
        Xs[lr][lc + 2] = xv.z; Xs[lr][lc + 3] = xv.w;

        float4 wv = *reinterpret_cast<const float4*>(&W[(size_t)(n0 + lr) * NN + k0 + lc]);
        Wv[lr][lc + 0] = wv.x; Wv[lr][lc + 1] = wv.y;
        Wv[lr][lc + 2] = wv.z; Wv[lr][lc + 3] = wv.w;

        float4 wm = *reinterpret_cast<const float4*>(&W[(size_t)(512 + n0 + lr) * NN + k0 + lc]);
        Wm[lr][lc + 0] = wm.x; Wm[lr][lc + 1] = wm.y;
        Wm[lr][lc + 2] = wm.z; Wm[lr][lc + 3] = wm.w;

        __syncthreads();

        #pragma unroll
        for (int kk = 0; kk < BK; kk++) {
            float x0 = Xs[rl][kk],     x1 = Xs[rl + 1][kk];
            float v0 = Wv[nl][kk],     v1 = Wv[nl + 1][kk];
            float m0 = Wm[nl][kk],     m1 = Wm[nl + 1][kk];
            av[0][0] += x0 * v0;  av[0][1] += x0 * v1;
            av[1][0] += x1 * v0;  av[1][1] += x1 * v1;
            am[0][0] += x0 * m0;  am[0][1] += x0 * m1;
            am[1][0] += x1 * m0;  am[1][1] += x1 * m1;
        }
        __syncthreads();
    }

    #pragma unroll
    for (int rr = 0; rr < 2; rr++) {
        #pragma unroll
        for (int nn = 0; nn < 2; nn++) {
            const int row = row0 + rl + rr;
            const int n   = n0 + nl + nn;
            float v  = av[rr][nn] + b[n];
            float m  = am[rr][nn] + b[512 + n];
            float sp = (v > 20.f) ? v : log1pf(expf(v));   // softplus, overflow-safe
            const int idx = row * NN + n;
            outM[idx] = m;
            outS[idx] = m + sqrtf(sp) * eps[idx];
            g_sp[idx] = sp;                                // diag scratch; std_mat untouched
        }
    }
}

// Scatter diagonal entries [base, base + gridDim*THREADS) over the zeroed std_mat
__global__ __launch_bounds__(THREADS)
void diag_fixup_range(float* __restrict__ out, unsigned base)
{
    float* __restrict__ outD = out + 2 * SAMPLE_ELEMS;
    const unsigned i = base + blockIdx.x * THREADS + threadIdx.x;
    outD[(size_t)i * NN + (i & 511u)] = g_sp[i];
}

extern "C" void kernel_launch(void* const* d_in, const int* in_sizes, int n_in,
                              void* d_out, int out_size)
{
    const float* x   = (const float*)d_in[0];
    const float* W   = (const float*)d_in[1];
    const float* b   = (const float*)d_in[2];
    const float* eps = (const float*)d_in[3];
    float* out = (float*)d_out;

    (void)in_sizes; (void)n_in; (void)out_size;

    // One-time resources, created on the first (correctness) call — before graph capture.
    static cudaStream_t s_cmp  = nullptr;
    static cudaEvent_t  e_fork = nullptr;
    static cudaEvent_t  e_msA  = nullptr;
    static cudaEvent_t  e_gemm = nullptr;
    static cudaEvent_t  e_fixA = nullptr;
    if (s_cmp == nullptr) {
        cudaStreamCreateWithFlags(&s_cmp, cudaStreamNonBlocking);
        cudaEventCreateWithFlags(&e_fork, cudaEventDisableTiming);
        cudaEventCreateWithFlags(&e_msA,  cudaEventDisableTiming);
        cudaEventCreateWithFlags(&e_gemm, cudaEventDisableTiming);
        cudaEventCreateWithFlags(&e_fixA, cudaEventDisableTiming);
    }

    char* std_base = reinterpret_cast<char*>(out + 2 * SAMPLE_ELEMS);

    // Fork compute branch
    cudaEventRecord(e_fork, 0);
    cudaStreamWaitEvent(s_cmp, e_fork, 0);

    // Compute branch: direct GEMM (sample, mu, softplus scratch) — hidden under fill
    gaussian_sampler_gemm<<<NB_GEMM, THREADS, 0, s_cmp>>>(x, W, b, eps, out);
    cudaEventRecord(e_gemm, s_cmp);

    // Legacy stream: two-phase engine fill (fast path proven in R4)
    cudaMemsetAsync(std_base, 0, MSA_BYTES);                         // first 160 MB
    cudaEventRecord(e_msA, 0);
    cudaMemsetAsync(std_base + MSA_BYTES, 0, STD_BYTES - MSA_BYTES); // last 96 MB

    // Pipelined fixup A on compute stream: after gemm (stream order) + msetA (event)
    cudaStreamWaitEvent(s_cmp, e_msA, 0);
    diag_fixup_range<<<FIXA_BLOCKS, THREADS, 0, s_cmp>>>(out, 0u);
    cudaEventRecord(e_fixA, s_cmp);

    // Join everything into the legacy stream, then tail fixup B
    cudaStreamWaitEvent(0, e_gemm, 0);
    cudaStreamWaitEvent(0, e_fixA, 0);
    diag_fixup_range<<<FIXB_BLOCKS, THREADS>>>(out, DIAG_SPLIT);
}